// round 5
// baseline (speedup 1.0000x reference)
#include <cuda_runtime.h>
#include <cuda_fp16.h>
#include <cstdint>

#define BB   32
#define TQQ  2000
#define TKK  512
#define EXNEG (-2000000)
#define PBLANK 0.36787944117144233f   /* e^-1 */
#define EF 2.7182818284590452f        /* e   */
#define FULLW 0xffffffffu

__device__ float    g_loss[BB];
__device__ float    g_logz[BB * TQQ];
__device__ unsigned g_ctr = 0;
// Pre-masked emissions e^{x+1} as half4 packed in uint2; 128 uint2 per row.
__device__ uint2    g_emit[(size_t)BB * TQQ * 128];

__device__ __forceinline__ float2 h2f_(unsigned u) {
    __half2 h = *reinterpret_cast<__half2*>(&u);
    return __half22float2(h);
}

// ---------------------------------------------------------------------------
// Kernel 1: per-row logZ = log(e^-1 + sum exp(x))  AND  emission store
//           g_emit[b,t,j] = (j<kl) ? half(e^{x+1}) : 0
// ---------------------------------------------------------------------------
__global__ __launch_bounds__(256) void zlog_kernel(const float* __restrict__ attn,
                                                   const int* __restrict__ in_lens,
                                                   const int* __restrict__ out_lens) {
    int b    = blockIdx.y;
    int warp = threadIdx.x >> 5;
    int lane = threadIdx.x & 31;
    int t    = blockIdx.x * 8 + warp;
    if (t >= TQQ) return;
    int kl = min(max(in_lens[b], 1), TKK);
    int ql = min(max(out_lens[b], 1), TQQ);
    if (t >= ql) return;

    const float4* row  = (const float4*)(attn + ((size_t)b * TQQ + t) * TKK);
    uint2*        erow = g_emit + ((size_t)b * TQQ + t) * 128;
    float s = 0.f;
#pragma unroll
    for (int k = 0; k < 4; k++) {
        float4 v = __ldg(row + lane + 32 * k);
        int j = 4 * (lane + 32 * k);
        float a0 = (j + 0 < kl) ? __expf(v.x) : 0.f;
        float a1 = (j + 1 < kl) ? __expf(v.y) : 0.f;
        float a2 = (j + 2 < kl) ? __expf(v.z) : 0.f;
        float a3 = (j + 3 < kl) ? __expf(v.w) : 0.f;
        s += (a0 + a1) + (a2 + a3);
        __half2 p01 = __floats2half2_rn(a0 * EF, a1 * EF);
        __half2 p23 = __floats2half2_rn(a2 * EF, a3 * EF);
        uint2 w;
        w.x = *reinterpret_cast<unsigned*>(&p01);
        w.y = *reinterpret_cast<unsigned*>(&p23);
        erow[lane + 32 * k] = w;
    }
#pragma unroll
    for (int o = 16; o; o >>= 1) s += __shfl_xor_sync(FULLW, s, o);
    if (lane == 0) g_logz[b * TQQ + t] = __logf(PBLANK + s);
}

// ---------------------------------------------------------------------------
// Kernel 2: CTC forward recursion, B-domain, precomputed fp16 emissions,
// 4 steps per exchange, per-thread block floating point, 8-row prefetch.
// 128 threads/block; thread tid owns states 8*tid..8*tid+7.
// ---------------------------------------------------------------------------
__global__ __launch_bounds__(128, 1) void dp_kernel(const float* __restrict__ attn,
                                                    const int* __restrict__ in_lens,
                                                    const int* __restrict__ out_lens,
                                                    float* __restrict__ out) {
    __shared__ float xch[2][5][12];   // [parity][warp+1][slot]; slot row 0 = zeros
    __shared__ float sm_even[513];
    __shared__ float sm_odd[513];
    __shared__ int   sm_ex[513];
    __shared__ float red[128];

    int b    = blockIdx.x;
    int tid  = threadIdx.x;
    int lane = tid & 31;
    int warp = tid >> 5;
    int kl = min(max(in_lens[b], 1), TKK);
    int ql = min(max(out_lens[b], 1), TQQ);

    const uint2* ob = g_emit + (size_t)b * TQQ * 128 + tid;               // own 4 cols
    const uint2* hb = g_emit + (size_t)b * TQQ * 128 + (tid ? tid - 1 : 0); // left 4 cols

    if (tid < 2) {
#pragma unroll
        for (int k = 0; k < 12; k++) xch[tid][0][k] = 0.f;
        xch[tid][0][8] = __int_as_float(EXNEG);
    }

    // ---- row 0 init (B_0 = A_0) ----
    float c8[8];
#pragma unroll
    for (int k = 0; k < 8; k++) c8[k] = 0.f;
    float a1024 = 0.f;
    int   exo   = EXNEG;
    if (tid == 0) {
        c8[0] = PBLANK;
        c8[1] = __expf(__ldg(attn + (size_t)b * TQQ * TKK));
        exo = 0;
    }

    // ---- prefetch rows 1..8 (own) and halo rows for both groups ----
    int qm = ql - 1;
    uint2 ou0 = __ldg(ob + (size_t)min(1, qm) * 128);
    uint2 ou1 = __ldg(ob + (size_t)min(2, qm) * 128);
    uint2 ou2 = __ldg(ob + (size_t)min(3, qm) * 128);
    uint2 ou3 = __ldg(ob + (size_t)min(4, qm) * 128);
    uint2 ou4 = __ldg(ob + (size_t)min(5, qm) * 128);
    uint2 ou5 = __ldg(ob + (size_t)min(6, qm) * 128);
    uint2 ou6 = __ldg(ob + (size_t)min(7, qm) * 128);
    uint2 ou7 = __ldg(ob + (size_t)min(8, qm) * 128);
    uint2 hu0 = __ldg(hb + (size_t)min(1, qm) * 128);
    uint2 hu1 = __ldg(hb + (size_t)min(2, qm) * 128);
    uint2 hu2 = __ldg(hb + (size_t)min(3, qm) * 128);
    uint2 hu3 = __ldg(hb + (size_t)min(5, qm) * 128);
    uint2 hu4 = __ldg(hb + (size_t)min(6, qm) * 128);
    uint2 hu5 = __ldg(hb + (size_t)min(7, qm) * 128);

    int t = 1;

#define PAIRS(DST, SRC, J, EM)                                                 \
    { float se_ = SRC[J] + SRC[J - 1]; DST[J] = se_;                           \
      DST[J + 1] = (SRC[J + 1] + se_) * (EM); }

#define GROUP(O0, O1, O2, O3, H0, H1, H2, REFILL, GUARDED)                     \
    {                                                                          \
        float2 r_;                                                             \
        r_ = h2f_((O0).x); float e00 = r_.x, e01 = r_.y;                       \
        r_ = h2f_((O0).y); float e02 = r_.x, e03 = r_.y;                       \
        r_ = h2f_((O1).x); float e10 = r_.x, e11 = r_.y;                       \
        r_ = h2f_((O1).y); float e12 = r_.x, e13 = r_.y;                       \
        r_ = h2f_((O2).x); float e20 = r_.x, e21 = r_.y;                       \
        r_ = h2f_((O2).y); float e22 = r_.x, e23 = r_.y;                       \
        r_ = h2f_((O3).x); float e30 = r_.x, e31 = r_.y;                       \
        r_ = h2f_((O3).y); float e32 = r_.x, e33 = r_.y;                       \
        float f01, f02, f03, f12, f13, f23;                                    \
        r_ = h2f_((H0).x); f01 = r_.y;                                         \
        r_ = h2f_((H0).y); f02 = r_.x; f03 = r_.y;                             \
        r_ = h2f_((H1).y); f12 = r_.x; f13 = r_.y;                             \
        r_ = h2f_((H2).y); f23 = r_.y;                                         \
        if (REFILL) {                                                          \
            (O0) = __ldg(ob + (size_t)min(t + 8,  qm) * 128);                  \
            (O1) = __ldg(ob + (size_t)min(t + 9,  qm) * 128);                  \
            (O2) = __ldg(ob + (size_t)min(t + 10, qm) * 128);                  \
            (O3) = __ldg(ob + (size_t)min(t + 11, qm) * 128);                  \
            (H0) = __ldg(hb + (size_t)min(t + 8,  qm) * 128);                  \
            (H1) = __ldg(hb + (size_t)min(t + 9,  qm) * 128);                  \
            (H2) = __ldg(hb + (size_t)min(t + 10, qm) * 128);                  \
        }                                                                      \
        int p_ = ((t - 1) >> 2) & 1;                                           \
        if (lane == 31) {                                                      \
            float* wb = xch[p_][warp + 1];                                     \
            wb[0] = c8[0]; wb[1] = c8[1]; wb[2] = c8[2]; wb[3] = c8[3];        \
            wb[4] = c8[4]; wb[5] = c8[5]; wb[6] = c8[6]; wb[7] = c8[7];        \
            wb[8] = __int_as_float(exo);                                       \
        }                                                                      \
        __syncthreads();                                                       \
        float h_[8]; int he_;                                                  \
        h_[0] = __shfl_up_sync(FULLW, c8[0], 1);                               \
        h_[1] = __shfl_up_sync(FULLW, c8[1], 1);                               \
        h_[2] = __shfl_up_sync(FULLW, c8[2], 1);                               \
        h_[3] = __shfl_up_sync(FULLW, c8[3], 1);                               \
        h_[4] = __shfl_up_sync(FULLW, c8[4], 1);                               \
        h_[5] = __shfl_up_sync(FULLW, c8[5], 1);                               \
        h_[6] = __shfl_up_sync(FULLW, c8[6], 1);                               \
        h_[7] = __shfl_up_sync(FULLW, c8[7], 1);                               \
        he_  = __shfl_up_sync(FULLW, exo, 1);                                  \
        if (lane == 0) {                                                       \
            const float* rb = xch[p_][warp];                                   \
            h_[0] = rb[0]; h_[1] = rb[1]; h_[2] = rb[2]; h_[3] = rb[3];        \
            h_[4] = rb[4]; h_[5] = rb[5]; h_[6] = rb[6]; h_[7] = rb[7];        \
            he_ = __float_as_int(rb[8]);                                       \
        }                                                                      \
        int bse = max(exo, he_);                                               \
        int d0_ = 127 + (he_ - bse); if (d0_ < 0) d0_ = 0;                     \
        int d1_ = 127 + (exo - bse); if (d1_ < 0) d1_ = 0;                     \
        float sh_ = __int_as_float(d0_ << 23);                                 \
        float so_ = __int_as_float(d1_ << 23);                                 \
        float A_[16], B_[16];                                                  \
        A_[0] = h_[0] * sh_; A_[1] = h_[1] * sh_;                              \
        A_[2] = h_[2] * sh_; A_[3] = h_[3] * sh_;                              \
        A_[4] = h_[4] * sh_; A_[5] = h_[5] * sh_;                              \
        A_[6] = h_[6] * sh_; A_[7] = h_[7] * sh_;                              \
        A_[8]  = c8[0] * so_; A_[9]  = c8[1] * so_;                            \
        A_[10] = c8[2] * so_; A_[11] = c8[3] * so_;                            \
        A_[12] = c8[4] * so_; A_[13] = c8[5] * so_;                            \
        A_[14] = c8[6] * so_; A_[15] = c8[7] * so_;                            \
        float n4 = a1024 * so_;                                                \
        if (!(GUARDED) || (t + 0 < ql)) {                                      \
            PAIRS(B_, A_, 2, f01) PAIRS(B_, A_, 4, f02) PAIRS(B_, A_, 6, f03)  \
            PAIRS(B_, A_, 8, e00) PAIRS(B_, A_, 10, e01)                       \
            PAIRS(B_, A_, 12, e02) PAIRS(B_, A_, 14, e03)                      \
            n4 = n4 + A_[15];                                                  \
        } else {                                                               \
            _Pragma("unroll")                                                  \
            for (int j_ = 2; j_ < 16; j_++) B_[j_] = A_[j_];                   \
        }                                                                      \
        if (!(GUARDED) || (t + 1 < ql)) {                                      \
            PAIRS(A_, B_, 4, f12) PAIRS(A_, B_, 6, f13)                        \
            PAIRS(A_, B_, 8, e10) PAIRS(A_, B_, 10, e11)                       \
            PAIRS(A_, B_, 12, e12) PAIRS(A_, B_, 14, e13)                      \
            n4 = n4 + B_[15];                                                  \
        } else {                                                               \
            _Pragma("unroll")                                                  \
            for (int j_ = 4; j_ < 16; j_++) A_[j_] = B_[j_];                   \
        }                                                                      \
        if (!(GUARDED) || (t + 2 < ql)) {                                      \
            PAIRS(B_, A_, 6, f23)                                              \
            PAIRS(B_, A_, 8, e20) PAIRS(B_, A_, 10, e21)                       \
            PAIRS(B_, A_, 12, e22) PAIRS(B_, A_, 14, e23)                      \
            n4 = n4 + A_[15];                                                  \
        } else {                                                               \
            _Pragma("unroll")                                                  \
            for (int j_ = 6; j_ < 16; j_++) B_[j_] = A_[j_];                   \
        }                                                                      \
        if (!(GUARDED) || (t + 3 < ql)) {                                      \
            PAIRS(A_, B_, 8, e30) PAIRS(A_, B_, 10, e31)                       \
            PAIRS(A_, B_, 12, e32) PAIRS(A_, B_, 14, e33)                      \
            n4 = n4 + B_[15];                                                  \
        } else {                                                               \
            _Pragma("unroll")                                                  \
            for (int j_ = 8; j_ < 16; j_++) A_[j_] = B_[j_];                   \
        }                                                                      \
        float m_ = fmaxf(fmaxf(fmaxf(A_[8], A_[9]), fmaxf(A_[10], A_[11])),    \
                         fmaxf(fmaxf(A_[12], A_[13]), fmaxf(A_[14], A_[15]))); \
        m_ = fmaxf(m_, n4);                                                    \
        int kk_ = ((__float_as_int(m_) >> 23) & 255) - 127;                    \
        float sc_ = __int_as_float((127 - kk_) << 23);                         \
        c8[0] = A_[8]  * sc_; c8[1] = A_[9]  * sc_;                            \
        c8[2] = A_[10] * sc_; c8[3] = A_[11] * sc_;                            \
        c8[4] = A_[12] * sc_; c8[5] = A_[13] * sc_;                            \
        c8[6] = A_[14] * sc_; c8[7] = A_[15] * sc_;                            \
        a1024 = n4 * sc_;                                                      \
        exo = (m_ > 0.f) ? (bse + kk_) : EXNEG;                                \
        t += 4;                                                                \
    }

    while (t + 7 < ql) {
        GROUP(ou0, ou1, ou2, ou3, hu0, hu1, hu2, 1, 0)
        GROUP(ou4, ou5, ou6, ou7, hu3, hu4, hu5, 1, 0)
    }
    if (t + 3 < ql) {
        GROUP(ou0, ou1, ou2, ou3, hu0, hu1, hu2, 0, 0)
        if (t < ql) { GROUP(ou4, ou5, ou6, ou7, hu3, hu4, hu5, 0, 1) }
    } else if (t < ql) {
        GROUP(ou0, ou1, ou2, ou3, hu0, hu1, hu2, 0, 1)
    }

    // ---- epilogue ----
#pragma unroll
    for (int k = 0; k < 4; k++) {
        sm_even[tid * 4 + k] = c8[2 * k];
        sm_odd [tid * 4 + k] = c8[2 * k + 1];
        sm_ex  [tid * 4 + k] = exo;
    }
    if (tid == 127) { sm_even[512] = a1024; sm_odd[512] = 0.f; sm_ex[512] = exo; }

    float lz = 0.f;
    for (int tt = tid; tt < ql; tt += 128) lz += g_logz[b * TQQ + tt];
    red[tid] = lz;
    __syncthreads();
#pragma unroll
    for (int s = 64; s; s >>= 1) {
        if (tid < s) red[tid] += red[tid + s];
        __syncthreads();
    }

    if (tid == 0) {
        float mE = sm_even[kl];     int eE = sm_ex[kl];       // state 2kl
        float mL = sm_odd[kl - 1];  int eL = sm_ex[kl - 1];   // state 2kl-1
        double ll;
        if (mE == 0.f && mL == 0.f) {
            ll = -1e9;
        } else {
            int eM = max(mE > 0.f ? eE : EXNEG, mL > 0.f ? eL : EXNEG);
            double s2 = 0.0;
            if (mE > 0.f) s2 += (double)mE * exp2((double)(eE - eM));
            if (mL > 0.f) s2 += (double)mL * exp2((double)(eL - eM));
            ll = log(s2) + (double)eM * 0.6931471805599453;
        }
        ll -= (double)red[0];          // - sum_t log Z_t
        ll -= (double)(ql - 1);        // undo B = A * e^t rescale
        g_loss[b] = (float)(-ll / (double)kl);

        __threadfence();
        unsigned prev = atomicAdd(&g_ctr, 1u);
        if (prev == BB - 1) {
            g_ctr = 0;
            __threadfence();
            float s = 0.f;
            for (int bb = 0; bb < BB; bb++) s += g_loss[bb];
            out[0] = s / (float)BB;
        }
    }
}

extern "C" void kernel_launch(void* const* d_in, const int* in_sizes, int n_in,
                              void* d_out, int out_size) {
    const float* attn     = (const float*)d_in[0];
    const int*   in_lens  = (const int*)d_in[1];
    const int*   out_lens = (const int*)d_in[2];

    zlog_kernel<<<dim3((TQQ + 7) / 8, BB), 256>>>(attn, in_lens, out_lens);
    dp_kernel<<<BB, 128>>>(attn, in_lens, out_lens, (float*)d_out);
}

// round 6
// speedup vs baseline: 1.0650x; 1.0650x over previous
#include <cuda_runtime.h>
#include <cstdint>

#define BB   32
#define TQQ  2000
#define TKK  512
#define EXNEG (-2000000)
#define PBLANK 0.36787944117144233f   /* e^-1 */
#define L2E 1.4426950408889634f
#define FULLW 0xffffffffu

__device__ float    g_loss[BB];
__device__ float    g_logz[BB * TQQ];
__device__ unsigned g_ctr = 0;

__device__ __forceinline__ float ex2f_(float x) {
    float r;
    asm("ex2.approx.ftz.f32 %0, %1;" : "=f"(r) : "f"(x));
    return r;
}

// ---------------------------------------------------------------------------
// Kernel 1: per-row log partition  logZ = log(e^-1 + sum_{j<kl} exp(x))
// ---------------------------------------------------------------------------
__global__ __launch_bounds__(256) void zlog_kernel(const float* __restrict__ attn,
                                                   const int* __restrict__ in_lens,
                                                   const int* __restrict__ out_lens) {
    int b    = blockIdx.y;
    int warp = threadIdx.x >> 5;
    int lane = threadIdx.x & 31;
    int t    = blockIdx.x * 8 + warp;
    if (t >= TQQ) return;
    int kl = min(max(in_lens[b], 1), TKK);
    int ql = min(max(out_lens[b], 1), TQQ);
    if (t >= ql) return;

    const float4* row = (const float4*)(attn + ((size_t)b * TQQ + t) * TKK);
    float s = 0.f;
#pragma unroll
    for (int k = 0; k < 4; k++) {
        float4 v = __ldg(row + lane + 32 * k);
        int j = 4 * (lane + 32 * k);
        float a0 = (j + 0 < kl) ? __expf(v.x) : 0.f;
        float a1 = (j + 1 < kl) ? __expf(v.y) : 0.f;
        float a2 = (j + 2 < kl) ? __expf(v.z) : 0.f;
        float a3 = (j + 3 < kl) ? __expf(v.w) : 0.f;
        s += (a0 + a1) + (a2 + a3);
    }
#pragma unroll
    for (int o = 16; o; o >>= 1) s += __shfl_xor_sync(FULLW, s, o);
    if (lane == 0) g_logz[b * TQQ + t] = __logf(PBLANK + s);
}

// ---------------------------------------------------------------------------
// Kernel 2: CTC forward recursion. B-domain (blank folded out), 4 steps per
// exchange/barrier, per-thread block floating point, 8-row prefetch,
// emissions software-pipelined one group ahead (issued under the barrier's
// deferred-blocking window). 128 threads; thread i owns states 8i..8i+7.
// ---------------------------------------------------------------------------
__global__ __launch_bounds__(128, 1) void dp_kernel(const float* __restrict__ attn,
                                                    const int* __restrict__ in_lens,
                                                    const int* __restrict__ out_lens,
                                                    float* __restrict__ out) {
    __shared__ float4 xch4[2][5][4];  // [parity][warp+1][rec]; rec = c8(8),exo,f(6),pad
    __shared__ float sm_even[513];
    __shared__ float sm_odd[513];
    __shared__ int   sm_ex[513];
    __shared__ float red[128];

    int b    = blockIdx.x;
    int tid  = threadIdx.x;
    int lane = tid & 31;
    int warp = tid >> 5;
    int kl = min(max(in_lens[b], 1), TKK);
    int ql = min(max(out_lens[b], 1), TQQ);

    const float4* base4 = (const float4*)(attn + (size_t)b * TQQ * TKK) + tid;

    bool mk0 = (tid * 4 + 0) < kl;
    bool mk1 = (tid * 4 + 1) < kl;
    bool mk2 = (tid * 4 + 2) < kl;
    bool mk3 = (tid * 4 + 3) < kl;

    if (tid < 2) {
        xch4[tid][0][0] = make_float4(0.f, 0.f, 0.f, 0.f);
        xch4[tid][0][1] = make_float4(0.f, 0.f, 0.f, 0.f);
        xch4[tid][0][2] = make_float4(__int_as_float(EXNEG), 0.f, 0.f, 0.f);
        xch4[tid][0][3] = make_float4(0.f, 0.f, 0.f, 0.f);
    }

    // ---- row 0 init (B_0 = A_0) ----
    float4 x0 = __ldg(base4);
    float c8[8];
#pragma unroll
    for (int k = 0; k < 8; k++) c8[k] = 0.f;
    float a1024 = 0.f;
    int   exo   = EXNEG;
    if (tid == 0) { c8[0] = PBLANK; c8[1] = __expf(x0.x); exo = 0; }

    // ---- prefetch rows 1..8 ----
    int qm = ql - 1;
    float4 xs0 = __ldg(base4 + (size_t)min(1, qm) * 128);
    float4 xs1 = __ldg(base4 + (size_t)min(2, qm) * 128);
    float4 xs2 = __ldg(base4 + (size_t)min(3, qm) * 128);
    float4 xs3 = __ldg(base4 + (size_t)min(4, qm) * 128);
    float4 xs4 = __ldg(base4 + (size_t)min(5, qm) * 128);
    float4 xs5 = __ldg(base4 + (size_t)min(6, qm) * 128);
    float4 xs6 = __ldg(base4 + (size_t)min(7, qm) * 128);
    float4 xs7 = __ldg(base4 + (size_t)min(8, qm) * 128);

    int t = 1;

#define EMIT(XC, MK) ((MK) ? ex2f_(fmaf((XC), L2E, L2E)) : 0.f)
#define EMITALL(E, S0, S1, S2, S3)                                             \
    {                                                                          \
        E[0]  = EMIT((S0).x, mk0); E[1]  = EMIT((S0).y, mk1);                  \
        E[2]  = EMIT((S0).z, mk2); E[3]  = EMIT((S0).w, mk3);                  \
        E[4]  = EMIT((S1).x, mk0); E[5]  = EMIT((S1).y, mk1);                  \
        E[6]  = EMIT((S1).z, mk2); E[7]  = EMIT((S1).w, mk3);                  \
        E[8]  = EMIT((S2).x, mk0); E[9]  = EMIT((S2).y, mk1);                  \
        E[10] = EMIT((S2).z, mk2); E[11] = EMIT((S2).w, mk3);                  \
        E[12] = EMIT((S3).x, mk0); E[13] = EMIT((S3).y, mk1);                  \
        E[14] = EMIT((S3).z, mk2); E[15] = EMIT((S3).w, mk3);                  \
    }
#define PAIRS(DST, SRC, J, EM)                                                 \
    { float se_ = SRC[J] + SRC[J - 1]; DST[J] = se_;                           \
      DST[J + 1] = (SRC[J + 1] + se_) * (EM); }

#define GROUP(EC, EN, N0, N1, N2, N3, R0, R1, R2, R3, REFILL, GUARDED)         \
    {                                                                          \
        /* phase 1: register shfls (no barrier needed) */                      \
        float f01 = __shfl_up_sync(FULLW, EC[1], 1);                           \
        float f02 = __shfl_up_sync(FULLW, EC[2], 1);                           \
        float f03 = __shfl_up_sync(FULLW, EC[3], 1);                           \
        float f12 = __shfl_up_sync(FULLW, EC[6], 1);                           \
        float f13 = __shfl_up_sync(FULLW, EC[7], 1);                           \
        float f23 = __shfl_up_sync(FULLW, EC[11], 1);                          \
        float h_[8]; int he_;                                                  \
        h_[0] = __shfl_up_sync(FULLW, c8[0], 1);                               \
        h_[1] = __shfl_up_sync(FULLW, c8[1], 1);                               \
        h_[2] = __shfl_up_sync(FULLW, c8[2], 1);                               \
        h_[3] = __shfl_up_sync(FULLW, c8[3], 1);                               \
        h_[4] = __shfl_up_sync(FULLW, c8[4], 1);                               \
        h_[5] = __shfl_up_sync(FULLW, c8[5], 1);                               \
        h_[6] = __shfl_up_sync(FULLW, c8[6], 1);                               \
        h_[7] = __shfl_up_sync(FULLW, c8[7], 1);                               \
        he_  = __shfl_up_sync(FULLW, exo, 1);                                  \
        int p_ = ((t - 1) >> 2) & 1;                                           \
        if (lane == 31) {                                                      \
            float4* wb = xch4[p_][warp + 1];                                   \
            wb[0] = make_float4(c8[0], c8[1], c8[2], c8[3]);                   \
            wb[1] = make_float4(c8[4], c8[5], c8[6], c8[7]);                   \
            wb[2] = make_float4(__int_as_float(exo), EC[1], EC[2], EC[3]);     \
            wb[3] = make_float4(EC[6], EC[7], EC[11], 0.f);                    \
        }                                                                      \
        __syncthreads();                                                       \
        /* phase 2: independent work under the barrier's deferred window */    \
        EMITALL(EN, N0, N1, N2, N3)                                            \
        if (REFILL) {                                                          \
            (R0) = __ldg(base4 + (size_t)min(t + 8,  qm) * 128);               \
            (R1) = __ldg(base4 + (size_t)min(t + 9,  qm) * 128);               \
            (R2) = __ldg(base4 + (size_t)min(t + 10, qm) * 128);               \
            (R3) = __ldg(base4 + (size_t)min(t + 11, qm) * 128);               \
        }                                                                      \
        /* phase 3: boundary merge (first smem consumer after bar) */          \
        if (lane == 0) {                                                       \
            const float4* rb = xch4[p_][warp];                                 \
            float4 q0 = rb[0], q1 = rb[1], q2 = rb[2], q3 = rb[3];             \
            h_[0] = q0.x; h_[1] = q0.y; h_[2] = q0.z; h_[3] = q0.w;            \
            h_[4] = q1.x; h_[5] = q1.y; h_[6] = q1.z; h_[7] = q1.w;            \
            he_ = __float_as_int(q2.x);                                        \
            f01 = q2.y; f02 = q2.z; f03 = q2.w;                                \
            f12 = q3.x; f13 = q3.y; f23 = q3.z;                                \
        }                                                                      \
        /* phase 4: align + 4 DP levels + renorm */                            \
        int bse = max(exo, he_);                                               \
        int d0_ = 127 + (he_ - bse); if (d0_ < 0) d0_ = 0;                     \
        int d1_ = 127 + (exo - bse); if (d1_ < 0) d1_ = 0;                     \
        float sh_ = __int_as_float(d0_ << 23);                                 \
        float so_ = __int_as_float(d1_ << 23);                                 \
        float A_[16], B_[16];                                                  \
        A_[0] = h_[0] * sh_; A_[1] = h_[1] * sh_;                              \
        A_[2] = h_[2] * sh_; A_[3] = h_[3] * sh_;                              \
        A_[4] = h_[4] * sh_; A_[5] = h_[5] * sh_;                              \
        A_[6] = h_[6] * sh_; A_[7] = h_[7] * sh_;                              \
        A_[8]  = c8[0] * so_; A_[9]  = c8[1] * so_;                            \
        A_[10] = c8[2] * so_; A_[11] = c8[3] * so_;                            \
        A_[12] = c8[4] * so_; A_[13] = c8[5] * so_;                            \
        A_[14] = c8[6] * so_; A_[15] = c8[7] * so_;                            \
        float n4 = a1024 * so_;                                                \
        if (!(GUARDED) || (t + 0 < ql)) {                                      \
            PAIRS(B_, A_, 2, f01) PAIRS(B_, A_, 4, f02) PAIRS(B_, A_, 6, f03)  \
            PAIRS(B_, A_, 8, EC[0]) PAIRS(B_, A_, 10, EC[1])                   \
            PAIRS(B_, A_, 12, EC[2]) PAIRS(B_, A_, 14, EC[3])                  \
            n4 = n4 + A_[15];                                                  \
        } else {                                                               \
            _Pragma("unroll")                                                  \
            for (int j_ = 2; j_ < 16; j_++) B_[j_] = A_[j_];                   \
        }                                                                      \
        if (!(GUARDED) || (t + 1 < ql)) {                                      \
            PAIRS(A_, B_, 4, f12) PAIRS(A_, B_, 6, f13)                        \
            PAIRS(A_, B_, 8, EC[4]) PAIRS(A_, B_, 10, EC[5])                   \
            PAIRS(A_, B_, 12, EC[6]) PAIRS(A_, B_, 14, EC[7])                  \
            n4 = n4 + B_[15];                                                  \
        } else {                                                               \
            _Pragma("unroll")                                                  \
            for (int j_ = 4; j_ < 16; j_++) A_[j_] = B_[j_];                   \
        }                                                                      \
        if (!(GUARDED) || (t + 2 < ql)) {                                      \
            PAIRS(B_, A_, 6, f23)                                              \
            PAIRS(B_, A_, 8, EC[8]) PAIRS(B_, A_, 10, EC[9])                   \
            PAIRS(B_, A_, 12, EC[10]) PAIRS(B_, A_, 14, EC[11])                \
            n4 = n4 + A_[15];                                                  \
        } else {                                                               \
            _Pragma("unroll")                                                  \
            for (int j_ = 6; j_ < 16; j_++) B_[j_] = A_[j_];                   \
        }                                                                      \
        if (!(GUARDED) || (t + 3 < ql)) {                                      \
            PAIRS(A_, B_, 8, EC[12]) PAIRS(A_, B_, 10, EC[13])                 \
            PAIRS(A_, B_, 12, EC[14]) PAIRS(A_, B_, 14, EC[15])                \
            n4 = n4 + B_[15];                                                  \
        } else {                                                               \
            _Pragma("unroll")                                                  \
            for (int j_ = 8; j_ < 16; j_++) A_[j_] = B_[j_];                   \
        }                                                                      \
        float m_ = fmaxf(fmaxf(fmaxf(A_[8], A_[9]), fmaxf(A_[10], A_[11])),    \
                         fmaxf(fmaxf(A_[12], A_[13]), fmaxf(A_[14], A_[15]))); \
        m_ = fmaxf(m_, n4);                                                    \
        int kk_ = ((__float_as_int(m_) >> 23) & 255) - 127;                    \
        float sc_ = __int_as_float((127 - kk_) << 23);                         \
        c8[0] = A_[8]  * sc_; c8[1] = A_[9]  * sc_;                            \
        c8[2] = A_[10] * sc_; c8[3] = A_[11] * sc_;                            \
        c8[4] = A_[12] * sc_; c8[5] = A_[13] * sc_;                            \
        c8[6] = A_[14] * sc_; c8[7] = A_[15] * sc_;                            \
        a1024 = n4 * sc_;                                                      \
        exo = (m_ > 0.f) ? (bse + kk_) : EXNEG;                                \
        t += 4;                                                                \
    }

    // ---- emission pipeline warmup: eA holds rows t..t+3 (= 1..4) ----
    float eA[16], eB[16];
    EMITALL(eA, xs0, xs1, xs2, xs3)

    while (t + 7 < ql) {
        GROUP(eA, eB, xs4, xs5, xs6, xs7, xs0, xs1, xs2, xs3, 1, 0)
        GROUP(eB, eA, xs0, xs1, xs2, xs3, xs4, xs5, xs6, xs7, 1, 0)
    }
    if (t + 3 < ql) {
        GROUP(eA, eB, xs4, xs5, xs6, xs7, xs0, xs1, xs2, xs3, 0, 0)
        if (t < ql) { GROUP(eB, eA, xs0, xs1, xs2, xs3, xs4, xs5, xs6, xs7, 0, 1) }
    } else if (t < ql) {
        GROUP(eA, eB, xs4, xs5, xs6, xs7, xs0, xs1, xs2, xs3, 0, 1)
    }

    // ---- epilogue ----
#pragma unroll
    for (int k = 0; k < 4; k++) {
        sm_even[tid * 4 + k] = c8[2 * k];
        sm_odd [tid * 4 + k] = c8[2 * k + 1];
        sm_ex  [tid * 4 + k] = exo;
    }
    if (tid == 127) { sm_even[512] = a1024; sm_odd[512] = 0.f; sm_ex[512] = exo; }

    float lz = 0.f;
    for (int tt = tid; tt < ql; tt += 128) lz += g_logz[b * TQQ + tt];
    red[tid] = lz;
    __syncthreads();
#pragma unroll
    for (int s = 64; s; s >>= 1) {
        if (tid < s) red[tid] += red[tid + s];
        __syncthreads();
    }

    if (tid == 0) {
        float mE = sm_even[kl];     int eE = sm_ex[kl];       // state 2kl
        float mL = sm_odd[kl - 1];  int eL = sm_ex[kl - 1];   // state 2kl-1
        double ll;
        if (mE == 0.f && mL == 0.f) {
            ll = -1e9;
        } else {
            int eM = max(mE > 0.f ? eE : EXNEG, mL > 0.f ? eL : EXNEG);
            double s2 = 0.0;
            if (mE > 0.f) s2 += (double)mE * exp2((double)(eE - eM));
            if (mL > 0.f) s2 += (double)mL * exp2((double)(eL - eM));
            ll = log(s2) + (double)eM * 0.6931471805599453;
        }
        ll -= (double)red[0];          // - sum_t log Z_t
        ll -= (double)(ql - 1);        // undo B = A * e^t rescale
        g_loss[b] = (float)(-ll / (double)kl);

        __threadfence();
        unsigned prev = atomicAdd(&g_ctr, 1u);
        if (prev == BB - 1) {
            g_ctr = 0;
            __threadfence();
            float s = 0.f;
            for (int bb = 0; bb < BB; bb++) s += g_loss[bb];
            out[0] = s / (float)BB;
        }
    }
}

extern "C" void kernel_launch(void* const* d_in, const int* in_sizes, int n_in,
                              void* d_out, int out_size) {
    const float* attn     = (const float*)d_in[0];
    const int*   in_lens  = (const int*)d_in[1];
    const int*   out_lens = (const int*)d_in[2];

    zlog_kernel<<<dim3((TQQ + 7) / 8, BB), 256>>>(attn, in_lens, out_lens);
    dp_kernel<<<BB, 128>>>(attn, in_lens, out_lens, (float*)d_out);
}